// round 1
// baseline (speedup 1.0000x reference)
#include <cuda_runtime.h>

// Problem constants
#define NB 128   // batch
#define CC 64    // in channels
#define TT 128   // time
#define VV 25    // vertices
#define RR 8     // rel channels
#define OC 64    // out channels

// ---- scratch (device globals: no allocation allowed) ----
__device__ float g_xm[NB * CC * VV];           // mean over T   (819 KB)
__device__ float g_top[(size_t)NB * OC * VV * VV];  // top tensor (20.5 MB)

// ============================================================
// K1: xm[n,c,v] = mean_t x[n,c,t,v]
// one CTA per (n,c); coalesced stage + deterministic reduction
// ============================================================
__global__ void k_mean(const float* __restrict__ x) {
    __shared__ float xs[TT * VV];        // 3200 floats
    __shared__ float part[4][VV];
    const int b = blockIdx.x;            // n*CC + c
    const float* px = x + (size_t)b * (TT * VV);
    const int tid = threadIdx.x;         // 128 threads

    #pragma unroll
    for (int i = tid; i < TT * VV; i += 128) xs[i] = px[i];
    __syncthreads();

    if (tid < 100) {
        const int v = tid % VV, q = tid / VV;   // q in [0,4)
        float s = 0.f;
        #pragma unroll
        for (int t = 0; t < 32; t++) s += xs[(q * 32 + t) * VV + v];
        part[q][v] = s;
    }
    __syncthreads();
    if (tid < VV) {
        float s = (part[0][tid] + part[1][tid]) + (part[2][tid] + part[3][tid]);
        g_xm[b * VV + tid] = s * (1.0f / TT);
    }
}

// ============================================================
// K2: top[n,o,u,v] = ALPHA*(sum_r w4[o,r]*tanh(x1[n,r,u]-x2[n,r,v]) + b4[o]) + A[u,v]
// one CTA per n
// ============================================================
__global__ void k_top(const float* __restrict__ A,
                      const float* __restrict__ w1, const float* __restrict__ b1,
                      const float* __restrict__ w2, const float* __restrict__ b2,
                      const float* __restrict__ w4, const float* __restrict__ b4) {
    __shared__ float xm_s[CC * VV];      // 1600
    __shared__ float x1_s[RR * VV];      // 200
    __shared__ float x2_s[RR * VV];      // 200
    __shared__ float d_s[RR * VV * VV];  // 5000
    __shared__ float w4_s[OC * RR];      // 512
    const int n = blockIdx.x;
    const int tid = threadIdx.x;         // 256 threads

    for (int i = tid; i < CC * VV; i += 256) xm_s[i] = g_xm[n * CC * VV + i];
    for (int i = tid; i < OC * RR; i += 256) w4_s[i] = w4[i];
    __syncthreads();

    if (tid < RR * VV) {
        const int r = tid / VV, v = tid % VV;
        float a1 = b1[r], a2 = b2[r];
        #pragma unroll 8
        for (int c = 0; c < CC; c++) {
            const float xv = xm_s[c * VV + v];
            a1 = fmaf(w1[r * CC + c], xv, a1);
            a2 = fmaf(w2[r * CC + c], xv, a2);
        }
        x1_s[tid] = a1;
        x2_s[tid] = a2;
    }
    __syncthreads();

    for (int i = tid; i < RR * VV * VV; i += 256) {
        const int r = i / (VV * VV), rem = i % (VV * VV);
        const int u = rem / VV, v = rem % VV;
        d_s[i] = tanhf(x1_s[r * VV + u] - x2_s[r * VV + v]);
    }
    __syncthreads();

    for (int p = tid; p < VV * VV; p += 256) {
        float dr[RR];
        #pragma unroll
        for (int r = 0; r < RR; r++) dr[r] = d_s[r * VV * VV + p];
        const float av = A[p];
        float* dst = g_top + (size_t)n * OC * VV * VV + p;
        #pragma unroll 4
        for (int o = 0; o < OC; o++) {
            float s = b4[o];
            #pragma unroll
            for (int r = 0; r < RR; r++) s = fmaf(w4_s[o * RR + r], dr[r], s);
            dst[o * VV * VV] = s * 1.0f /*ALPHA*/ + av;
        }
    }
}

// ============================================================
// K3 (hot): per (n, o-group of 16):
//   x3[o,t,v] = b3[o] + sum_c w3[o,c]*x[n,c,t,v]       (Phase B)
//   out[n,o,t,u] = sum_v top[n,o,u,v]*x3[o,t,v]        (Phase C)
// ============================================================
#define OO_CTA 16          // o's per CTA (4 groups)
#define TTILE  8           // timesteps per tile
#define JD     (TTILE * VV)   // 200

// dynamic smem layout (in floats):
#define OFF_TOP  0                         // 16*625 = 10000
#define OFF_W3   10000                     // 16*64  = 1024
#define OFF_B3   11024                     // 16
#define OFF_X    11040                     // 64*200 = 12800 (16B aligned)
#define OFF_X3T  23840                     // 16*200 = 3200  (16B aligned)
#define SMEM_FLOATS 27040
#define SMEM_BYTES  (SMEM_FLOATS * 4)      // 108160 B -> 2 CTAs/SM

__global__ __launch_bounds__(256, 2)
void k_main(const float* __restrict__ x, const float* __restrict__ w3,
            const float* __restrict__ b3, float* __restrict__ out) {
    extern __shared__ float sm[];
    float* top_s = sm + OFF_TOP;
    float* w3_s  = sm + OFF_W3;
    float* b3_s  = sm + OFF_B3;
    float* x_s   = sm + OFF_X;
    float* x3t_s = sm + OFF_X3T;

    const int og  = blockIdx.x;           // 0..3
    const int n   = blockIdx.y;           // 0..127
    const int tid = threadIdx.x;          // 256
    const int obase = og * OO_CTA;

    // per-CTA constants into smem
    const float* ptop = g_top + ((size_t)n * OC + obase) * (VV * VV);
    for (int i = tid; i < OO_CTA * VV * VV; i += 256) top_s[i] = ptop[i];
    for (int i = tid; i < OO_CTA * CC; i += 256) w3_s[i] = w3[obase * CC + i];
    if (tid < OO_CTA) b3_s[tid] = b3[obase + tid];

    const int ty   = tid >> 6;            // 0..3  -> 4 o's each (warp-uniform)
    const int tx   = tid & 63;            // 0..63 -> j columns
    const int warp = tid >> 5;            // 0..7  -> 2 o's each in Phase C
    const int lane = tid & 31;
    const int u    = (lane < VV) ? lane : 0;

    int  col[4];
    bool cval[4];
    #pragma unroll
    for (int jj = 0; jj < 4; jj++) {
        const int j = tx + 64 * jj;
        cval[jj] = (j < JD);
        col[jj]  = cval[jj] ? j : 0;
    }

    const float4* gx4 = reinterpret_cast<const float4*>(x) + (size_t)n * (CC * TT * VV / 4);
    // per-c row stride in float4: TT*VV/4 = 800

    __syncthreads();   // top/w3/b3 ready

    for (int t0 = 0; t0 < TT; t0 += TTILE) {
        // ---- Phase A: load x tile [64 c][200 j] as float4 (t0*25 % 4 == 0) ----
        const int tstart4 = (t0 * VV) >> 2;
        for (int i = tid; i < CC * (JD / 4); i += 256) {
            const int c = i / (JD / 4);
            const int q = i % (JD / 4);
            reinterpret_cast<float4*>(x_s)[c * (JD / 4) + q] = gx4[c * 800 + tstart4 + q];
        }
        __syncthreads();   // x_s ready; also guarantees prior Phase C done

        // ---- Phase B: x3 (4 o x 4 j register tile, 2 FMA / LDS) ----
        float acc[4][4];
        #pragma unroll
        for (int i = 0; i < 4; i++) {
            const float bb = b3_s[ty * 4 + i];
            #pragma unroll
            for (int jj = 0; jj < 4; jj++) acc[i][jj] = bb;
        }
        #pragma unroll 4
        for (int c = 0; c < CC; c++) {
            float w[4];
            #pragma unroll
            for (int i = 0; i < 4; i++) w[i] = w3_s[(ty * 4 + i) * CC + c];
            float xv[4];
            #pragma unroll
            for (int jj = 0; jj < 4; jj++) xv[jj] = x_s[c * JD + col[jj]];
            #pragma unroll
            for (int i = 0; i < 4; i++)
                #pragma unroll
                for (int jj = 0; jj < 4; jj++)
                    acc[i][jj] = fmaf(w[i], xv[jj], acc[i][jj]);
        }
        // store transposed: x3t[oo][v][tt] so Phase C reads tt-contiguous float4
        #pragma unroll
        for (int i = 0; i < 4; i++) {
            const int oo = ty * 4 + i;
            #pragma unroll
            for (int jj = 0; jj < 4; jj++) {
                if (cval[jj]) {
                    const int j = col[jj];
                    const int tt = j / VV, v = j % VV;
                    x3t_s[oo * JD + v * TTILE + tt] = acc[i][jj];
                }
            }
        }
        __syncthreads();   // x3t ready

        // ---- Phase C: out[o,t,u] = sum_v top[o,u,v]*x3[o,t,v] ----
        #pragma unroll
        for (int k = 0; k < 2; k++) {
            const int oo = warp * 2 + k;
            float oa[TTILE] = {0, 0, 0, 0, 0, 0, 0, 0};
            const float*  tp = top_s + oo * (VV * VV) + u * VV;      // stride-25: conflict-free
            const float4* xr = reinterpret_cast<const float4*>(x3t_s + oo * JD);
            #pragma unroll 5
            for (int v = 0; v < VV; v++) {
                const float  tv = tp[v];
                const float4 a  = xr[v * 2];       // tt 0..3 (broadcast)
                const float4 b  = xr[v * 2 + 1];   // tt 4..7 (broadcast)
                oa[0] = fmaf(tv, a.x, oa[0]);
                oa[1] = fmaf(tv, a.y, oa[1]);
                oa[2] = fmaf(tv, a.z, oa[2]);
                oa[3] = fmaf(tv, a.w, oa[3]);
                oa[4] = fmaf(tv, b.x, oa[4]);
                oa[5] = fmaf(tv, b.y, oa[5]);
                oa[6] = fmaf(tv, b.z, oa[6]);
                oa[7] = fmaf(tv, b.w, oa[7]);
            }
            if (lane < VV) {
                const int o = obase + oo;
                float* po = out + ((size_t)(n * OC + o) * TT + t0) * VV + u;
                #pragma unroll
                for (int tt = 0; tt < TTILE; tt++) po[tt * VV] = oa[tt];
            }
        }
        // no trailing barrier: next iteration's post-A barrier covers the
        // x3t WAR hazard (Phase A doesn't touch x3t/top)
    }
}

// ============================================================
// launch
// ============================================================
extern "C" void kernel_launch(void* const* d_in, const int* in_sizes, int n_in,
                              void* d_out, int out_size) {
    const float* x  = (const float*)d_in[0];
    const float* A  = (const float*)d_in[1];
    const float* w1 = (const float*)d_in[2];
    const float* b1 = (const float*)d_in[3];
    const float* w2 = (const float*)d_in[4];
    const float* b2 = (const float*)d_in[5];
    const float* w3 = (const float*)d_in[6];
    const float* b3 = (const float*)d_in[7];
    const float* w4 = (const float*)d_in[8];
    const float* b4 = (const float*)d_in[9];
    float* out = (float*)d_out;

    cudaFuncSetAttribute(k_main, cudaFuncAttributeMaxDynamicSharedMemorySize, SMEM_BYTES);

    k_mean<<<NB * CC, 128>>>(x);
    k_top<<<NB, 256>>>(A, w1, b1, w2, b2, w4, b4);
    k_main<<<dim3(4, NB), 256, SMEM_BYTES>>>(x, w3, b3, out);
}